// round 8
// baseline (speedup 1.0000x reference)
#include <cuda_runtime.h>
#include <mma.h>
#include <math.h>
#include <stdint.h>

using namespace nvcuda;

#define N_NODES   100000
#define DEG       16
#define IN_DIM    128
#define OUT_DIM   32
#define EPS       1e-8f

// scratch (device globals: no allocation allowed in kernel_launch)
__device__ float g_z[N_NODES * OUT_DIM];
__device__ float g_inorm[N_NODES];          // 1 / max(||z_i||, EPS)

__device__ __forceinline__ float f2tf32(float x) {
    float r;
    asm("cvt.rna.tf32.f32 %0, %1;" : "=f"(r) : "f"(x));
    return r;
}

// ---------------------------------------------------------------------------
// Kernel 1: z = h @ W^T via wmma TF32 (m16n16k8), fused inverse row norms.
// One CTA per 64-row tile (1563 CTAs), 256 threads = 8 warps.
// ~50KB smem/CTA -> 4 CTAs/SM = 32 warps/SM (2x R7) for latency hiding.
// Warp w: m-tile (w&3)*16, n-tile (w>>2)*16; 16 k-steps, b-frags loaded from
// smem inside the loop (no register preload -> ~48 regs).
// Dynamic smem (floats):
//   Ws  [32][132] @ 0      (16896 B)
//   hs  [64][132] @ 4224   (33792 B)   zsm [64][36] ALIASES hs (dead after MMA)
// total 50688 B.
// ---------------------------------------------------------------------------
#define LDH 132
#define LDZ 36
#define GEMM_SMEM_BYTES 50688

__global__ __launch_bounds__(256, 4) void gemm_wmma_kernel(
    const float* __restrict__ h, const float* __restrict__ W, int N)
{
    extern __shared__ float sm[];
    float* Ws  = sm;            // [32][132]
    float* hs  = sm + 4224;     // [64][132]
    float* zsm = sm + 4224;     // [64][36]  (aliases hs; used after sync)

    const int tid  = threadIdx.x;
    const int wid  = tid >> 5;
    const int m0   = (wid & 3) * 16;
    const int n0   = (wid >> 2) * 16;
    const int row0 = blockIdx.x * 64;
    const unsigned FULL = 0xffffffffu;

    // ---- stage W -> tf32-rounded smem (coalesced float4) ----
    const float4* W4 = reinterpret_cast<const float4*>(W);
    #pragma unroll
    for (int i = 0; i < 4; i++) {
        int f  = tid + i * 256;            // float4 index 0..1023
        int n  = f >> 5;
        int k4 = f & 31;
        float4 v = __ldg(&W4[n * 32 + k4]);
        float* d = &Ws[n * LDH + k4 * 4];
        d[0] = f2tf32(v.x); d[1] = f2tf32(v.y);
        d[2] = f2tf32(v.z); d[3] = f2tf32(v.w);
    }

    // ---- load 64-row h tile -> tf32-rounded smem ----
    const float4* h4 = reinterpret_cast<const float4*>(h);
    #pragma unroll
    for (int i = 0; i < 8; i++) {
        int f    = tid + i * 256;          // float4 index 0..2047
        int r    = f >> 5;                 // 0..63
        int k4   = f & 31;                 // 0..31
        int grow = row0 + r;
        if (grow >= N) grow = N - 1;
        float4 v = __ldg(&h4[grow * 32 + k4]);
        float* d = &hs[r * LDH + k4 * 4];
        d[0] = f2tf32(v.x); d[1] = f2tf32(v.y);
        d[2] = f2tf32(v.z); d[3] = f2tf32(v.w);
    }
    __syncthreads();

    // ---- wmma: 1 m-tile x 1 n-tile x 16 k-steps per warp ----
    wmma::fragment<wmma::accumulator, 16, 16, 8, float> c0;
    wmma::fill_fragment(c0, 0.0f);
    wmma::fragment<wmma::matrix_a, 16, 16, 8, wmma::precision::tf32,
                   wmma::row_major> a0;
    wmma::fragment<wmma::matrix_b, 16, 16, 8, wmma::precision::tf32,
                   wmma::col_major> b0;
    #pragma unroll
    for (int ks = 0; ks < 16; ks++) {
        wmma::load_matrix_sync(a0, &hs[m0 * LDH + ks * 8], LDH);
        wmma::load_matrix_sync(b0, &Ws[n0 * LDH + ks * 8], LDH);
        wmma::mma_sync(c0, a0, b0, c0);
    }
    __syncthreads();                       // hs reads done -> zsm may overwrite

    wmma::store_matrix_sync(&zsm[m0 * LDZ + n0], c0, LDZ, wmma::mem_row_major);
    __syncthreads();

    // ---- epilogue: coalesced z write + inverse norms ----
    // thread t: row = t>>2 (0..63), quarter q = t&3 -> cols q*8..q*8+7
    int row = tid >> 2;
    int q   = tid & 3;
    float4 z4[2];
    z4[0] = *reinterpret_cast<const float4*>(&zsm[row * LDZ + q * 8]);
    z4[1] = *reinterpret_cast<const float4*>(&zsm[row * LDZ + q * 8 + 4]);
    float ss = z4[0].x * z4[0].x + z4[0].y * z4[0].y
             + z4[0].z * z4[0].z + z4[0].w * z4[0].w
             + z4[1].x * z4[1].x + z4[1].y * z4[1].y
             + z4[1].z * z4[1].z + z4[1].w * z4[1].w;
    ss += __shfl_xor_sync(FULL, ss, 1);
    ss += __shfl_xor_sync(FULL, ss, 2);
    int grow = row0 + row;
    if (grow < N) {
        float4* dst = reinterpret_cast<float4*>(&g_z[grow * OUT_DIM + q * 8]);
        dst[0] = z4[0];
        dst[1] = z4[1];
        if (q == 0)
            g_inorm[grow] = 1.0f / fmaxf(sqrtf(ss), EPS);
    }
}

// ---------------------------------------------------------------------------
// Kernel 2: per-node cosine attention + softmax + weighted aggregation.
// Half-warp per node; hierarchical multi-reduce (30 shfl/warp for 32 dots).
// __launch_bounds__(256,5): cap regs at 51 -> 40 warps/SM (62% occ).
// ---------------------------------------------------------------------------
__global__ __launch_bounds__(256, 5) void edge_agg_kernel(
    const float* __restrict__ beta_p, const int* __restrict__ src,
    float* __restrict__ out, int N)
{
    __shared__ float alpha_sm[8][32];

    const int warp_id = (blockIdx.x * blockDim.x + threadIdx.x) >> 5;
    if (warp_id * 2 >= N) return;

    const int w    = threadIdx.x >> 5;
    const int lane = threadIdx.x & 31;
    const int half = lane >> 4;
    const int hl   = lane & 15;
    int node = warp_id * 2 + half;
    const bool valid = (node < N);
    if (!valid) node = N - 1;

    const unsigned FULL = 0xffffffffu;
    const float beta = __ldg(beta_p);

    const float2 zd    = *reinterpret_cast<const float2*>(&g_z[node * OUT_DIM + 2 * hl]);
    const float inv_nd = g_inorm[node];

    const int4* sp = reinterpret_cast<const int4*>(src + node * DEG);
    int4 s0 = __ldg(sp + 0);
    int4 s1 = __ldg(sp + 1);
    int4 s2 = __ldg(sp + 2);
    int4 s3 = __ldg(sp + 3);
    int si[DEG] = { s0.x, s0.y, s0.z, s0.w,  s1.x, s1.y, s1.z, s1.w,
                    s2.x, s2.y, s2.z, s2.w,  s3.x, s3.y, s3.z, s3.w };

    // own-edge src (coalesced) -> per-edge cosine scale
    const int sid_own = __ldg(src + node * DEG + hl);
    const float cc = __ldg(&g_inorm[sid_own]) * inv_nd;

    // 4-bit bit-reversal (involution): lane hl ends holding edge hl's dot
    constexpr int REV4[16] = {0,8,4,12, 2,10,6,14, 1,9,5,13, 3,11,7,15};

    float2 v[DEG];
    #pragma unroll
    for (int k = 0; k < DEG; k++)
        v[k] = *reinterpret_cast<const float2*>(&g_z[si[REV4[k]] * OUT_DIM + 2 * hl]);

    float p[DEG];
    #pragma unroll
    for (int k = 0; k < DEG; k++)
        p[k] = fmaf(v[k].x, zd.x, v[k].y * zd.y);

    const bool b8 = (hl & 8) != 0;
    const bool b4 = (hl & 4) != 0;
    const bool b2 = (hl & 2) != 0;
    const bool b1 = (hl & 1) != 0;

    float s[8];
    #pragma unroll
    for (int i = 0; i < 8; i++) {
        float a = p[2 * i]     + __shfl_xor_sync(FULL, p[2 * i], 8);
        float b = p[2 * i + 1] + __shfl_xor_sync(FULL, p[2 * i + 1], 8);
        s[i] = b8 ? b : a;
    }
    float q[4];
    #pragma unroll
    for (int i = 0; i < 4; i++) {
        float a = s[2 * i]     + __shfl_xor_sync(FULL, s[2 * i], 4);
        float b = s[2 * i + 1] + __shfl_xor_sync(FULL, s[2 * i + 1], 4);
        q[i] = b4 ? b : a;
    }
    float w2_[2];
    #pragma unroll
    for (int i = 0; i < 2; i++) {
        float a = q[2 * i]     + __shfl_xor_sync(FULL, q[2 * i], 2);
        float b = q[2 * i + 1] + __shfl_xor_sync(FULL, q[2 * i + 1], 2);
        w2_[i] = b2 ? b : a;
    }
    float xa = w2_[0] + __shfl_xor_sync(FULL, w2_[0], 1);
    float xb = w2_[1] + __shfl_xor_sync(FULL, w2_[1], 1);
    float dotv = b1 ? xb : xa;                 // raw dot of edge `hl`

    // softmax weight: exp(-beta(1-cos)) -> exp(beta*cos) (constant cancels);
    // beta in [0,1), cos <= 1 -> no overflow, no max subtraction needed.
    float esc = __expf(beta * (dotv * cc));

    float denom = esc;
    denom += __shfl_xor_sync(FULL, denom, 8);
    denom += __shfl_xor_sync(FULL, denom, 4);
    denom += __shfl_xor_sync(FULL, denom, 2);
    denom += __shfl_xor_sync(FULL, denom, 1);

    // publish esc in REV4-permuted order: slot j holds esc of edge REV4[j]
    alpha_sm[w][(lane & 16) | REV4[hl]] = esc;
    __syncwarp(FULL);

    const float4* ap = reinterpret_cast<const float4*>(&alpha_sm[w][lane & 16]);
    float ox = 0.f, oy = 0.f;
    #pragma unroll
    for (int k4 = 0; k4 < 4; k4++) {
        float4 a4 = ap[k4];
        ox = fmaf(a4.x, v[4 * k4 + 0].x, ox);
        oy = fmaf(a4.x, v[4 * k4 + 0].y, oy);
        ox = fmaf(a4.y, v[4 * k4 + 1].x, ox);
        oy = fmaf(a4.y, v[4 * k4 + 1].y, oy);
        ox = fmaf(a4.z, v[4 * k4 + 2].x, ox);
        oy = fmaf(a4.z, v[4 * k4 + 2].y, oy);
        ox = fmaf(a4.w, v[4 * k4 + 3].x, ox);
        oy = fmaf(a4.w, v[4 * k4 + 3].y, oy);
    }

    if (valid) {
        float invd = 1.0f / denom;
        *reinterpret_cast<float2*>(&out[node * OUT_DIM + 2 * hl]) =
            make_float2(ox * invd, oy * invd);
    }
}

extern "C" void kernel_launch(void* const* d_in, const int* in_sizes, int n_in,
                              void* d_out, int out_size)
{
    const float* h    = (const float*)d_in[0];   // [N, 128]
    const float* W    = (const float*)d_in[1];   // [32, 128]
    const float* beta = (const float*)d_in[2];   // [1]
    const int*   src  = (const int*)d_in[3];     // [E]
    float* out = (float*)d_out;

    int N = in_sizes[0] / IN_DIM;                // 100000
    int ntiles = (N + 63) / 64;                  // 1563

    cudaFuncSetAttribute(gemm_wmma_kernel,
                         cudaFuncAttributeMaxDynamicSharedMemorySize,
                         GEMM_SMEM_BYTES);
    gemm_wmma_kernel<<<ntiles, 256, GEMM_SMEM_BYTES>>>(h, W, N);

    int nwarps  = (N + 1) / 2;
    int nblocks = (nwarps + 7) / 8;              // 8 warps / block
    edge_agg_kernel<<<nblocks, 256>>>(beta, src, out, N);
}

// round 9
// speedup vs baseline: 1.0300x; 1.0300x over previous
#include <cuda_runtime.h>
#include <mma.h>
#include <math.h>
#include <stdint.h>

using namespace nvcuda;

#define N_NODES   100000
#define DEG       16
#define IN_DIM    128
#define OUT_DIM   32
#define EPS       1e-8f

// scratch (device globals: no allocation allowed in kernel_launch)
__device__ float g_z[N_NODES * OUT_DIM];
__device__ float g_inorm[N_NODES];          // 1 / max(||z_i||, EPS)

__device__ __forceinline__ float f2tf32(float x) {
    float r;
    asm("cvt.rna.tf32.f32 %0, %1;" : "=f"(r) : "f"(x));
    return r;
}

// ---------------------------------------------------------------------------
// Kernel 1: z = h @ W^T via wmma TF32 (m16n16k8), fused inverse row norms.
// PERSISTENT: 592 CTAs (4/SM), 256 threads = 8 warps, looping over 64-row
// tiles. W staged+converted once per CTA. ~50KB smem -> 4 CTAs/SM = 32
// warps/SM. Warp w: m-tile (w&3)*16, n-tile (w>>2)*16.
// Dynamic smem (floats):
//   Ws  [32][132] @ 0      (16896 B)
//   hs  [64][132] @ 4224   (33792 B)   zsm [64][36] ALIASES hs
// total 50688 B.
// ---------------------------------------------------------------------------
#define LDH 132
#define LDZ 36
#define GEMM_SMEM_BYTES 50688

__global__ __launch_bounds__(256, 4) void gemm_wmma_kernel(
    const float* __restrict__ h, const float* __restrict__ W, int N, int ntiles)
{
    extern __shared__ float sm[];
    float* Ws  = sm;            // [32][132]
    float* hs  = sm + 4224;     // [64][132]
    float* zsm = sm + 4224;     // [64][36]  (aliases hs; used after sync)

    const int tid = threadIdx.x;
    const int wid = tid >> 5;
    const int m0  = (wid & 3) * 16;
    const int n0  = (wid >> 2) * 16;
    const unsigned FULL = 0xffffffffu;

    // ---- stage W -> tf32-rounded smem (once per CTA) ----
    const float4* W4 = reinterpret_cast<const float4*>(W);
    #pragma unroll
    for (int i = 0; i < 4; i++) {
        int f  = tid + i * 256;            // float4 index 0..1023
        int n  = f >> 5;
        int k4 = f & 31;
        float4 v = __ldg(&W4[n * 32 + k4]);
        float* d = &Ws[n * LDH + k4 * 4];
        d[0] = f2tf32(v.x); d[1] = f2tf32(v.y);
        d[2] = f2tf32(v.z); d[3] = f2tf32(v.w);
    }

    const float4* h4 = reinterpret_cast<const float4*>(h);

    for (int t = blockIdx.x; t < ntiles; t += gridDim.x) {
        const int row0 = t * 64;
        __syncthreads();                   // Ws ready / prev zsm reads done

        // ---- load 64-row h tile -> tf32-rounded smem ----
        #pragma unroll
        for (int i = 0; i < 8; i++) {
            int f    = tid + i * 256;      // float4 index 0..2047
            int r    = f >> 5;             // 0..63
            int k4   = f & 31;             // 0..31
            int grow = row0 + r;
            if (grow >= N) grow = N - 1;
            float4 v = __ldg(&h4[grow * 32 + k4]);
            float* d = &hs[r * LDH + k4 * 4];
            d[0] = f2tf32(v.x); d[1] = f2tf32(v.y);
            d[2] = f2tf32(v.z); d[3] = f2tf32(v.w);
        }
        __syncthreads();

        // ---- wmma: 1 m-tile x 1 n-tile x 16 k-steps per warp ----
        wmma::fragment<wmma::accumulator, 16, 16, 8, float> c0;
        wmma::fill_fragment(c0, 0.0f);
        wmma::fragment<wmma::matrix_a, 16, 16, 8, wmma::precision::tf32,
                       wmma::row_major> a0;
        wmma::fragment<wmma::matrix_b, 16, 16, 8, wmma::precision::tf32,
                       wmma::col_major> b0;
        #pragma unroll
        for (int ks = 0; ks < 16; ks++) {
            wmma::load_matrix_sync(a0, &hs[m0 * LDH + ks * 8], LDH);
            wmma::load_matrix_sync(b0, &Ws[n0 * LDH + ks * 8], LDH);
            wmma::mma_sync(c0, a0, b0, c0);
        }
        __syncthreads();                   // hs reads done -> zsm may overwrite

        wmma::store_matrix_sync(&zsm[m0 * LDZ + n0], c0, LDZ, wmma::mem_row_major);
        __syncthreads();

        // ---- epilogue: coalesced z write + inverse norms ----
        int row = tid >> 2;
        int q   = tid & 3;
        float4 z4[2];
        z4[0] = *reinterpret_cast<const float4*>(&zsm[row * LDZ + q * 8]);
        z4[1] = *reinterpret_cast<const float4*>(&zsm[row * LDZ + q * 8 + 4]);
        float ss = z4[0].x * z4[0].x + z4[0].y * z4[0].y
                 + z4[0].z * z4[0].z + z4[0].w * z4[0].w
                 + z4[1].x * z4[1].x + z4[1].y * z4[1].y
                 + z4[1].z * z4[1].z + z4[1].w * z4[1].w;
        ss += __shfl_xor_sync(FULL, ss, 1);
        ss += __shfl_xor_sync(FULL, ss, 2);
        int grow = row0 + row;
        if (grow < N) {
            float4* dst = reinterpret_cast<float4*>(&g_z[grow * OUT_DIM + q * 8]);
            dst[0] = z4[0];
            dst[1] = z4[1];
            if (q == 0)
                g_inorm[grow] = 1.0f / fmaxf(sqrtf(ss), EPS);
        }
    }
}

// ---------------------------------------------------------------------------
// Kernel 2: per-node cosine attention + softmax + weighted aggregation.
// Half-warp per node; hierarchical multi-reduce (30 shfl/warp for 32 dots).
// denom computed from the smem alpha row during aggregation (no shfl).
// No launch_bounds cap (R8 showed the 48-reg cap causes spills).
// ---------------------------------------------------------------------------
__global__ __launch_bounds__(256) void edge_agg_kernel(
    const float* __restrict__ beta_p, const int* __restrict__ src,
    float* __restrict__ out, int N)
{
    __shared__ float alpha_sm[8][32];

    const int warp_id = (blockIdx.x * blockDim.x + threadIdx.x) >> 5;
    if (warp_id * 2 >= N) return;

    const int w    = threadIdx.x >> 5;
    const int lane = threadIdx.x & 31;
    const int half = lane >> 4;
    const int hl   = lane & 15;
    int node = warp_id * 2 + half;
    const bool valid = (node < N);
    if (!valid) node = N - 1;

    const unsigned FULL = 0xffffffffu;
    const float beta = __ldg(beta_p);

    const float2 zd    = *reinterpret_cast<const float2*>(&g_z[node * OUT_DIM + 2 * hl]);
    const float inv_nd = g_inorm[node];

    const int4* sp = reinterpret_cast<const int4*>(src + node * DEG);
    int4 s0 = __ldg(sp + 0);
    int4 s1 = __ldg(sp + 1);
    int4 s2 = __ldg(sp + 2);
    int4 s3 = __ldg(sp + 3);
    int si[DEG] = { s0.x, s0.y, s0.z, s0.w,  s1.x, s1.y, s1.z, s1.w,
                    s2.x, s2.y, s2.z, s2.w,  s3.x, s3.y, s3.z, s3.w };

    // own-edge src (coalesced) -> per-edge cosine scale
    const int sid_own = __ldg(src + node * DEG + hl);
    const float cc = __ldg(&g_inorm[sid_own]) * inv_nd;

    // 4-bit bit-reversal (involution): lane hl ends holding edge hl's dot
    constexpr int REV4[16] = {0,8,4,12, 2,10,6,14, 1,9,5,13, 3,11,7,15};

    float2 v[DEG];
    #pragma unroll
    for (int k = 0; k < DEG; k++)
        v[k] = *reinterpret_cast<const float2*>(&g_z[si[REV4[k]] * OUT_DIM + 2 * hl]);

    float p[DEG];
    #pragma unroll
    for (int k = 0; k < DEG; k++)
        p[k] = fmaf(v[k].x, zd.x, v[k].y * zd.y);

    const bool b8 = (hl & 8) != 0;
    const bool b4 = (hl & 4) != 0;
    const bool b2 = (hl & 2) != 0;
    const bool b1 = (hl & 1) != 0;

    float s[8];
    #pragma unroll
    for (int i = 0; i < 8; i++) {
        float a = p[2 * i]     + __shfl_xor_sync(FULL, p[2 * i], 8);
        float b = p[2 * i + 1] + __shfl_xor_sync(FULL, p[2 * i + 1], 8);
        s[i] = b8 ? b : a;
    }
    float q[4];
    #pragma unroll
    for (int i = 0; i < 4; i++) {
        float a = s[2 * i]     + __shfl_xor_sync(FULL, s[2 * i], 4);
        float b = s[2 * i + 1] + __shfl_xor_sync(FULL, s[2 * i + 1], 4);
        q[i] = b4 ? b : a;
    }
    float w2_[2];
    #pragma unroll
    for (int i = 0; i < 2; i++) {
        float a = q[2 * i]     + __shfl_xor_sync(FULL, q[2 * i], 2);
        float b = q[2 * i + 1] + __shfl_xor_sync(FULL, q[2 * i + 1], 2);
        w2_[i] = b2 ? b : a;
    }
    float xa = w2_[0] + __shfl_xor_sync(FULL, w2_[0], 1);
    float xb = w2_[1] + __shfl_xor_sync(FULL, w2_[1], 1);
    float dotv = b1 ? xb : xa;                 // raw dot of edge `hl`

    // softmax weight: exp(-beta(1-cos)) -> exp(beta*cos) (constant cancels);
    // beta in [0,1), cos <= 1 -> no overflow, no max subtraction needed.
    float esc = __expf(beta * (dotv * cc));

    // publish esc in REV4-permuted order: slot j holds esc of edge REV4[j]
    alpha_sm[w][(lane & 16) | REV4[hl]] = esc;
    __syncwarp(FULL);

    // aggregation + denom accumulated from the same smem reads (no shfl)
    const float4* ap = reinterpret_cast<const float4*>(&alpha_sm[w][lane & 16]);
    float ox = 0.f, oy = 0.f, denom = 0.f;
    #pragma unroll
    for (int k4 = 0; k4 < 4; k4++) {
        float4 a4 = ap[k4];
        denom += (a4.x + a4.y) + (a4.z + a4.w);
        ox = fmaf(a4.x, v[4 * k4 + 0].x, ox);
        oy = fmaf(a4.x, v[4 * k4 + 0].y, oy);
        ox = fmaf(a4.y, v[4 * k4 + 1].x, ox);
        oy = fmaf(a4.y, v[4 * k4 + 1].y, oy);
        ox = fmaf(a4.z, v[4 * k4 + 2].x, ox);
        oy = fmaf(a4.z, v[4 * k4 + 2].y, oy);
        ox = fmaf(a4.w, v[4 * k4 + 3].x, ox);
        oy = fmaf(a4.w, v[4 * k4 + 3].y, oy);
    }

    if (valid) {
        float invd = 1.0f / denom;
        *reinterpret_cast<float2*>(&out[node * OUT_DIM + 2 * hl]) =
            make_float2(ox * invd, oy * invd);
    }
}

extern "C" void kernel_launch(void* const* d_in, const int* in_sizes, int n_in,
                              void* d_out, int out_size)
{
    const float* h    = (const float*)d_in[0];   // [N, 128]
    const float* W    = (const float*)d_in[1];   // [32, 128]
    const float* beta = (const float*)d_in[2];   // [1]
    const int*   src  = (const int*)d_in[3];     // [E]
    float* out = (float*)d_out;

    int N = in_sizes[0] / IN_DIM;                // 100000
    int ntiles = (N + 63) / 64;                  // 1563

    cudaFuncSetAttribute(gemm_wmma_kernel,
                         cudaFuncAttributeMaxDynamicSharedMemorySize,
                         GEMM_SMEM_BYTES);
    int grid = 592;                              // 4 CTAs/SM * 148 SMs
    if (grid > ntiles) grid = ntiles;
    gemm_wmma_kernel<<<grid, 256, GEMM_SMEM_BYTES>>>(h, W, N, ntiles);

    int nwarps  = (N + 1) / 2;
    int nblocks = (nwarps + 7) / 8;              // 8 warps / block
    edge_agg_kernel<<<nblocks, 256>>>(beta, src, out, N);
}

// round 10
// speedup vs baseline: 1.0359x; 1.0058x over previous
#include <cuda_runtime.h>
#include <cuda_fp16.h>
#include <mma.h>
#include <math.h>
#include <stdint.h>

using namespace nvcuda;

#define N_NODES   100000
#define DEG       16
#define IN_DIM    128
#define OUT_DIM   32
#define EPS       1e-8f

// scratch (device globals: no allocation allowed in kernel_launch)
__device__ float   g_z[N_NODES * OUT_DIM];
__device__ __half2 g_zh[N_NODES * (OUT_DIM / 2)];   // fp16 copy for gathers
__device__ float   g_inorm[N_NODES];                // 1 / max(||z_i||, EPS)

__device__ __forceinline__ float f2tf32(float x) {
    float r;
    asm("cvt.rna.tf32.f32 %0, %1;" : "=f"(r) : "f"(x));
    return r;
}

// ---------------------------------------------------------------------------
// Kernel 1: z = h @ W^T via wmma TF32 (m16n16k8), fused inverse row norms.
// Non-persistent: one CTA per 64-row tile (1563 CTAs), 256 threads = 8 warps.
// ~50KB smem/CTA -> 4 CTAs/SM = 32 warps/SM.
// Warp w: m-tile (w&3)*16, n-tile (w>>2)*16; b-frags loaded per k-step.
// Epilogue writes z (fp32), z (fp16 packed), inverse norms.
// Dynamic smem (floats):
//   Ws  [32][132] @ 0      (16896 B)
//   hs  [64][132] @ 4224   (33792 B)   zsm [64][36] ALIASES hs
// total 50688 B.
// ---------------------------------------------------------------------------
#define LDH 132
#define LDZ 36
#define GEMM_SMEM_BYTES 50688

__global__ __launch_bounds__(256, 4) void gemm_wmma_kernel(
    const float* __restrict__ h, const float* __restrict__ W, int N)
{
    extern __shared__ float sm[];
    float* Ws  = sm;            // [32][132]
    float* hs  = sm + 4224;     // [64][132]
    float* zsm = sm + 4224;     // [64][36]  (aliases hs; used after sync)

    const int tid  = threadIdx.x;
    const int wid  = tid >> 5;
    const int m0   = (wid & 3) * 16;
    const int n0   = (wid >> 2) * 16;
    const int row0 = blockIdx.x * 64;
    const unsigned FULL = 0xffffffffu;

    // ---- stage W -> tf32-rounded smem (coalesced float4) ----
    const float4* W4 = reinterpret_cast<const float4*>(W);
    #pragma unroll
    for (int i = 0; i < 4; i++) {
        int f  = tid + i * 256;            // float4 index 0..1023
        int n  = f >> 5;
        int k4 = f & 31;
        float4 v = __ldg(&W4[n * 32 + k4]);
        float* d = &Ws[n * LDH + k4 * 4];
        d[0] = f2tf32(v.x); d[1] = f2tf32(v.y);
        d[2] = f2tf32(v.z); d[3] = f2tf32(v.w);
    }

    // ---- load 64-row h tile -> tf32-rounded smem ----
    const float4* h4 = reinterpret_cast<const float4*>(h);
    #pragma unroll
    for (int i = 0; i < 8; i++) {
        int f    = tid + i * 256;          // float4 index 0..2047
        int r    = f >> 5;                 // 0..63
        int k4   = f & 31;                 // 0..31
        int grow = row0 + r;
        if (grow >= N) grow = N - 1;
        float4 v = __ldg(&h4[grow * 32 + k4]);
        float* d = &hs[r * LDH + k4 * 4];
        d[0] = f2tf32(v.x); d[1] = f2tf32(v.y);
        d[2] = f2tf32(v.z); d[3] = f2tf32(v.w);
    }
    __syncthreads();

    // ---- wmma: 1 m-tile x 1 n-tile x 16 k-steps per warp ----
    wmma::fragment<wmma::accumulator, 16, 16, 8, float> c0;
    wmma::fill_fragment(c0, 0.0f);
    wmma::fragment<wmma::matrix_a, 16, 16, 8, wmma::precision::tf32,
                   wmma::row_major> a0;
    wmma::fragment<wmma::matrix_b, 16, 16, 8, wmma::precision::tf32,
                   wmma::col_major> b0;
    #pragma unroll
    for (int ks = 0; ks < 16; ks++) {
        wmma::load_matrix_sync(a0, &hs[m0 * LDH + ks * 8], LDH);
        wmma::load_matrix_sync(b0, &Ws[n0 * LDH + ks * 8], LDH);
        wmma::mma_sync(c0, a0, b0, c0);
    }
    __syncthreads();                       // hs reads done -> zsm may overwrite

    wmma::store_matrix_sync(&zsm[m0 * LDZ + n0], c0, LDZ, wmma::mem_row_major);
    __syncthreads();

    // ---- epilogue: coalesced z (fp32 + fp16) + inverse norms ----
    // thread t: row = t>>2 (0..63), quarter q = t&3 -> cols q*8..q*8+7
    int row = tid >> 2;
    int q   = tid & 3;
    float4 z4[2];
    z4[0] = *reinterpret_cast<const float4*>(&zsm[row * LDZ + q * 8]);
    z4[1] = *reinterpret_cast<const float4*>(&zsm[row * LDZ + q * 8 + 4]);
    float ss = z4[0].x * z4[0].x + z4[0].y * z4[0].y
             + z4[0].z * z4[0].z + z4[0].w * z4[0].w
             + z4[1].x * z4[1].x + z4[1].y * z4[1].y
             + z4[1].z * z4[1].z + z4[1].w * z4[1].w;
    ss += __shfl_xor_sync(FULL, ss, 1);
    ss += __shfl_xor_sync(FULL, ss, 2);
    int grow = row0 + row;
    if (grow < N) {
        float4* dst = reinterpret_cast<float4*>(&g_z[grow * OUT_DIM + q * 8]);
        dst[0] = z4[0];
        dst[1] = z4[1];
        // fp16 copy: 8 halves = 16B per thread, coalesced
        __half2 hx[4];
        hx[0] = __floats2half2_rn(z4[0].x, z4[0].y);
        hx[1] = __floats2half2_rn(z4[0].z, z4[0].w);
        hx[2] = __floats2half2_rn(z4[1].x, z4[1].y);
        hx[3] = __floats2half2_rn(z4[1].z, z4[1].w);
        *reinterpret_cast<uint4*>(&g_zh[grow * 16 + q * 4]) =
            *reinterpret_cast<const uint4*>(hx);
        if (q == 0)
            g_inorm[grow] = 1.0f / fmaxf(sqrtf(ss), EPS);
    }
}

// ---------------------------------------------------------------------------
// Kernel 2: per-node cosine attention + softmax + weighted aggregation.
// Half-warp per node; v gathered as __half2 (64B/row: half the wavefronts,
// half the registers of fp32). All math in fp32.
// ---------------------------------------------------------------------------
__global__ __launch_bounds__(256) void edge_agg_kernel(
    const float* __restrict__ beta_p, const int* __restrict__ src,
    float* __restrict__ out, int N)
{
    __shared__ float alpha_sm[8][32];

    const int warp_id = (blockIdx.x * blockDim.x + threadIdx.x) >> 5;
    if (warp_id * 2 >= N) return;

    const int w    = threadIdx.x >> 5;
    const int lane = threadIdx.x & 31;
    const int half = lane >> 4;
    const int hl   = lane & 15;
    int node = warp_id * 2 + half;
    const bool valid = (node < N);
    if (!valid) node = N - 1;

    const unsigned FULL = 0xffffffffu;
    const float beta = __ldg(beta_p);

    const float2 zd    = *reinterpret_cast<const float2*>(&g_z[node * OUT_DIM + 2 * hl]);
    const float inv_nd = g_inorm[node];

    const int4* sp = reinterpret_cast<const int4*>(src + node * DEG);
    int4 s0 = __ldg(sp + 0);
    int4 s1 = __ldg(sp + 1);
    int4 s2 = __ldg(sp + 2);
    int4 s3 = __ldg(sp + 3);
    int si[DEG] = { s0.x, s0.y, s0.z, s0.w,  s1.x, s1.y, s1.z, s1.w,
                    s2.x, s2.y, s2.z, s2.w,  s3.x, s3.y, s3.z, s3.w };

    // own-edge src (coalesced) -> per-edge cosine scale
    const int sid_own = __ldg(src + node * DEG + hl);
    const float cc = __ldg(&g_inorm[sid_own]) * inv_nd;

    // 4-bit bit-reversal (involution): lane hl ends holding edge hl's dot
    constexpr int REV4[16] = {0,8,4,12, 2,10,6,14, 1,9,5,13, 3,11,7,15};

    // gather src rows in fp16 (64B per row: 2 sectors vs 4 for fp32)
    __half2 v[DEG];
    #pragma unroll
    for (int k = 0; k < DEG; k++)
        v[k] = g_zh[si[REV4[k]] * 16 + hl];

    float p[DEG];
    #pragma unroll
    for (int k = 0; k < DEG; k++) {
        float2 vf = __half22float2(v[k]);
        p[k] = fmaf(vf.x, zd.x, vf.y * zd.y);
    }

    const bool b8 = (hl & 8) != 0;
    const bool b4 = (hl & 4) != 0;
    const bool b2 = (hl & 2) != 0;
    const bool b1 = (hl & 1) != 0;

    float s[8];
    #pragma unroll
    for (int i = 0; i < 8; i++) {
        float a = p[2 * i]     + __shfl_xor_sync(FULL, p[2 * i], 8);
        float b = p[2 * i + 1] + __shfl_xor_sync(FULL, p[2 * i + 1], 8);
        s[i] = b8 ? b : a;
    }
    float q[4];
    #pragma unroll
    for (int i = 0; i < 4; i++) {
        float a = s[2 * i]     + __shfl_xor_sync(FULL, s[2 * i], 4);
        float b = s[2 * i + 1] + __shfl_xor_sync(FULL, s[2 * i + 1], 4);
        q[i] = b4 ? b : a;
    }
    float w2_[2];
    #pragma unroll
    for (int i = 0; i < 2; i++) {
        float a = q[2 * i]     + __shfl_xor_sync(FULL, q[2 * i], 2);
        float b = q[2 * i + 1] + __shfl_xor_sync(FULL, q[2 * i + 1], 2);
        w2_[i] = b2 ? b : a;
    }
    float xa = w2_[0] + __shfl_xor_sync(FULL, w2_[0], 1);
    float xb = w2_[1] + __shfl_xor_sync(FULL, w2_[1], 1);
    float dotv = b1 ? xb : xa;                 // raw dot of edge `hl`

    // softmax weight: exp(-beta(1-cos)) -> exp(beta*cos) (constant cancels);
    // beta in [0,1), cos <= 1 -> no overflow, no max subtraction needed.
    float esc = __expf(beta * (dotv * cc));

    // publish esc in REV4-permuted order: slot j holds esc of edge REV4[j]
    alpha_sm[w][(lane & 16) | REV4[hl]] = esc;
    __syncwarp(FULL);

    // aggregation + denom accumulated from the same smem reads (no shfl)
    const float4* ap = reinterpret_cast<const float4*>(&alpha_sm[w][lane & 16]);
    float ox = 0.f, oy = 0.f, denom = 0.f;
    #pragma unroll
    for (int k4 = 0; k4 < 4; k4++) {
        float4 a4 = ap[k4];
        denom += (a4.x + a4.y) + (a4.z + a4.w);
        float2 v0 = __half22float2(v[4 * k4 + 0]);
        float2 v1 = __half22float2(v[4 * k4 + 1]);
        float2 v2 = __half22float2(v[4 * k4 + 2]);
        float2 v3 = __half22float2(v[4 * k4 + 3]);
        ox = fmaf(a4.x, v0.x, ox);  oy = fmaf(a4.x, v0.y, oy);
        ox = fmaf(a4.y, v1.x, ox);  oy = fmaf(a4.y, v1.y, oy);
        ox = fmaf(a4.z, v2.x, ox);  oy = fmaf(a4.z, v2.y, oy);
        ox = fmaf(a4.w, v3.x, ox);  oy = fmaf(a4.w, v3.y, oy);
    }

    if (valid) {
        float invd = 1.0f / denom;
        *reinterpret_cast<float2*>(&out[node * OUT_DIM + 2 * hl]) =
            make_float2(ox * invd, oy * invd);
    }
}

extern "C" void kernel_launch(void* const* d_in, const int* in_sizes, int n_in,
                              void* d_out, int out_size)
{
    const float* h    = (const float*)d_in[0];   // [N, 128]
    const float* W    = (const float*)d_in[1];   // [32, 128]
    const float* beta = (const float*)d_in[2];   // [1]
    const int*   src  = (const int*)d_in[3];     // [E]
    float* out = (float*)d_out;

    int N = in_sizes[0] / IN_DIM;                // 100000
    int ntiles = (N + 63) / 64;                  // 1563

    cudaFuncSetAttribute(gemm_wmma_kernel,
                         cudaFuncAttributeMaxDynamicSharedMemorySize,
                         GEMM_SMEM_BYTES);
    gemm_wmma_kernel<<<ntiles, 256, GEMM_SMEM_BYTES>>>(h, W, N);

    int nwarps  = (N + 1) / 2;
    int nblocks = (nwarps + 7) / 8;              // 8 warps / block
    edge_agg_kernel<<<nblocks, 256>>>(beta, src, out, N);
}

// round 11
// speedup vs baseline: 1.0964x; 1.0584x over previous
#include <cuda_runtime.h>
#include <cuda_fp16.h>
#include <mma.h>
#include <math.h>
#include <stdint.h>

using namespace nvcuda;

#define N_NODES   100000
#define DEG       16
#define IN_DIM    128
#define OUT_DIM   32
#define EPS       1e-8f

// scratch (device globals: no allocation allowed in kernel_launch)
__device__ __half2 g_zh[N_NODES * (OUT_DIM / 2)];   // z rows in fp16 (only copy)
__device__ float   g_inorm[N_NODES];                // 1 / max(||z_i||, EPS)

__device__ __forceinline__ float f2tf32(float x) {
    float r;
    asm("cvt.rna.tf32.f32 %0, %1;" : "=f"(r) : "f"(x));
    return r;
}

// ---------------------------------------------------------------------------
// Kernel 1: z = h @ W^T via wmma TF32 (m16n16k8), fused inverse row norms.
// Non-persistent: one CTA per 64-row tile (1563 CTAs), 256 threads = 8 warps.
// ~50KB smem/CTA -> 4 CTAs/SM = 32 warps/SM.
// Epilogue writes ONLY fp16 z + inverse norms (fp32 z array eliminated;
// norms still computed from fp32 accumulators).
// Dynamic smem (floats):
//   Ws  [32][132] @ 0      (16896 B)
//   hs  [64][132] @ 4224   (33792 B)   zsm [64][36] ALIASES hs
// total 50688 B.
// ---------------------------------------------------------------------------
#define LDH 132
#define LDZ 36
#define GEMM_SMEM_BYTES 50688

__global__ __launch_bounds__(256, 4) void gemm_wmma_kernel(
    const float* __restrict__ h, const float* __restrict__ W, int N)
{
    extern __shared__ float sm[];
    float* Ws  = sm;            // [32][132]
    float* hs  = sm + 4224;     // [64][132]
    float* zsm = sm + 4224;     // [64][36]  (aliases hs; used after sync)

    const int tid  = threadIdx.x;
    const int wid  = tid >> 5;
    const int m0   = (wid & 3) * 16;
    const int n0   = (wid >> 2) * 16;
    const int row0 = blockIdx.x * 64;
    const unsigned FULL = 0xffffffffu;

    // ---- stage W -> tf32-rounded smem (coalesced float4) ----
    const float4* W4 = reinterpret_cast<const float4*>(W);
    #pragma unroll
    for (int i = 0; i < 4; i++) {
        int f  = tid + i * 256;            // float4 index 0..1023
        int n  = f >> 5;
        int k4 = f & 31;
        float4 v = __ldg(&W4[n * 32 + k4]);
        float* d = &Ws[n * LDH + k4 * 4];
        d[0] = f2tf32(v.x); d[1] = f2tf32(v.y);
        d[2] = f2tf32(v.z); d[3] = f2tf32(v.w);
    }

    // ---- load 64-row h tile -> tf32-rounded smem ----
    const float4* h4 = reinterpret_cast<const float4*>(h);
    #pragma unroll
    for (int i = 0; i < 8; i++) {
        int f    = tid + i * 256;          // float4 index 0..2047
        int r    = f >> 5;                 // 0..63
        int k4   = f & 31;                 // 0..31
        int grow = row0 + r;
        if (grow >= N) grow = N - 1;
        float4 v = __ldg(&h4[grow * 32 + k4]);
        float* d = &hs[r * LDH + k4 * 4];
        d[0] = f2tf32(v.x); d[1] = f2tf32(v.y);
        d[2] = f2tf32(v.z); d[3] = f2tf32(v.w);
    }
    __syncthreads();

    // ---- wmma: 1 m-tile x 1 n-tile x 16 k-steps per warp ----
    wmma::fragment<wmma::accumulator, 16, 16, 8, float> c0;
    wmma::fill_fragment(c0, 0.0f);
    wmma::fragment<wmma::matrix_a, 16, 16, 8, wmma::precision::tf32,
                   wmma::row_major> a0;
    wmma::fragment<wmma::matrix_b, 16, 16, 8, wmma::precision::tf32,
                   wmma::col_major> b0;
    #pragma unroll
    for (int ks = 0; ks < 16; ks++) {
        wmma::load_matrix_sync(a0, &hs[m0 * LDH + ks * 8], LDH);
        wmma::load_matrix_sync(b0, &Ws[n0 * LDH + ks * 8], LDH);
        wmma::mma_sync(c0, a0, b0, c0);
    }
    __syncthreads();                       // hs reads done -> zsm may overwrite

    wmma::store_matrix_sync(&zsm[m0 * LDZ + n0], c0, LDZ, wmma::mem_row_major);
    __syncthreads();

    // ---- epilogue: fp16 z (coalesced) + inverse norms ----
    // thread t: row = t>>2 (0..63), quarter q = t&3 -> cols q*8..q*8+7
    int row = tid >> 2;
    int q   = tid & 3;
    float4 z4[2];
    z4[0] = *reinterpret_cast<const float4*>(&zsm[row * LDZ + q * 8]);
    z4[1] = *reinterpret_cast<const float4*>(&zsm[row * LDZ + q * 8 + 4]);
    float ss = z4[0].x * z4[0].x + z4[0].y * z4[0].y
             + z4[0].z * z4[0].z + z4[0].w * z4[0].w
             + z4[1].x * z4[1].x + z4[1].y * z4[1].y
             + z4[1].z * z4[1].z + z4[1].w * z4[1].w;
    ss += __shfl_xor_sync(FULL, ss, 1);
    ss += __shfl_xor_sync(FULL, ss, 2);
    int grow = row0 + row;
    if (grow < N) {
        __half2 hx[4];
        hx[0] = __floats2half2_rn(z4[0].x, z4[0].y);
        hx[1] = __floats2half2_rn(z4[0].z, z4[0].w);
        hx[2] = __floats2half2_rn(z4[1].x, z4[1].y);
        hx[3] = __floats2half2_rn(z4[1].z, z4[1].w);
        *reinterpret_cast<uint4*>(&g_zh[grow * 16 + q * 4]) =
            *reinterpret_cast<const uint4*>(hx);
        if (q == 0)
            g_inorm[grow] = 1.0f / fmaxf(sqrtf(ss), EPS);
    }
}

// ---------------------------------------------------------------------------
// Kernel 2: per-node cosine attention + softmax + weighted aggregation.
// Half-warp per node; v AND zd gathered as __half2. All math in fp32.
// ---------------------------------------------------------------------------
__global__ __launch_bounds__(256) void edge_agg_kernel(
    const float* __restrict__ beta_p, const int* __restrict__ src,
    float* __restrict__ out, int N)
{
    __shared__ float alpha_sm[8][32];

    const int warp_id = (blockIdx.x * blockDim.x + threadIdx.x) >> 5;
    if (warp_id * 2 >= N) return;

    const int w    = threadIdx.x >> 5;
    const int lane = threadIdx.x & 31;
    const int half = lane >> 4;
    const int hl   = lane & 15;
    int node = warp_id * 2 + half;
    const bool valid = (node < N);
    if (!valid) node = N - 1;

    const unsigned FULL = 0xffffffffu;
    const float beta = __ldg(beta_p);

    const float2 zd    = __half22float2(g_zh[node * 16 + hl]);
    const float inv_nd = g_inorm[node];

    const int4* sp = reinterpret_cast<const int4*>(src + node * DEG);
    int4 s0 = __ldg(sp + 0);
    int4 s1 = __ldg(sp + 1);
    int4 s2 = __ldg(sp + 2);
    int4 s3 = __ldg(sp + 3);
    int si[DEG] = { s0.x, s0.y, s0.z, s0.w,  s1.x, s1.y, s1.z, s1.w,
                    s2.x, s2.y, s2.z, s2.w,  s3.x, s3.y, s3.z, s3.w };

    // own-edge src (coalesced) -> per-edge cosine scale
    const int sid_own = __ldg(src + node * DEG + hl);
    const float cc = __ldg(&g_inorm[sid_own]) * inv_nd;

    // 4-bit bit-reversal (involution): lane hl ends holding edge hl's dot
    constexpr int REV4[16] = {0,8,4,12, 2,10,6,14, 1,9,5,13, 3,11,7,15};

    // gather src rows in fp16 (64B per row: 2 sectors)
    __half2 v[DEG];
    #pragma unroll
    for (int k = 0; k < DEG; k++)
        v[k] = g_zh[si[REV4[k]] * 16 + hl];

    float p[DEG];
    #pragma unroll
    for (int k = 0; k < DEG; k++) {
        float2 vf = __half22float2(v[k]);
        p[k] = fmaf(vf.x, zd.x, vf.y * zd.y);
    }

    const bool b8 = (hl & 8) != 0;
    const bool b4 = (hl & 4) != 0;
    const bool b2 = (hl & 2) != 0;
    const bool b1 = (hl & 1) != 0;

    float s[8];
    #pragma unroll
    for (int i = 0; i < 8; i++) {
        float a = p[2 * i]     + __shfl_xor_sync(FULL, p[2 * i], 8);
        float b = p[2 * i + 1] + __shfl_xor_sync(FULL, p[2 * i + 1], 8);
        s[i] = b8 ? b : a;
    }
    float q[4];
    #pragma unroll
    for (int i = 0; i < 4; i++) {
        float a = s[2 * i]     + __shfl_xor_sync(FULL, s[2 * i], 4);
        float b = s[2 * i + 1] + __shfl_xor_sync(FULL, s[2 * i + 1], 4);
        q[i] = b4 ? b : a;
    }
    float w2_[2];
    #pragma unroll
    for (int i = 0; i < 2; i++) {
        float a = q[2 * i]     + __shfl_xor_sync(FULL, q[2 * i], 2);
        float b = q[2 * i + 1] + __shfl_xor_sync(FULL, q[2 * i + 1], 2);
        w2_[i] = b2 ? b : a;
    }
    float xa = w2_[0] + __shfl_xor_sync(FULL, w2_[0], 1);
    float xb = w2_[1] + __shfl_xor_sync(FULL, w2_[1], 1);
    float dotv = b1 ? xb : xa;                 // raw dot of edge `hl`

    // softmax weight: exp(-beta(1-cos)) -> exp(beta*cos) (constant cancels);
    // beta in [0,1), cos <= 1 -> no overflow, no max subtraction needed.
    float esc = __expf(beta * (dotv * cc));

    // publish esc in REV4-permuted order: slot j holds esc of edge REV4[j]
    alpha_sm[w][(lane & 16) | REV4[hl]] = esc;
    __syncwarp(FULL);

    // aggregation + denom accumulated from the same smem reads (no shfl)
    const float4* ap = reinterpret_cast<const float4*>(&alpha_sm[w][lane & 16]);
    float ox = 0.f, oy = 0.f, denom = 0.f;
    #pragma unroll
    for (int k4 = 0; k4 < 4; k4++) {
        float4 a4 = ap[k4];
        denom += (a4.x + a4.y) + (a4.z + a4.w);
        float2 v0 = __half22float2(v[4 * k4 + 0]);
        float2 v1 = __half22float2(v[4 * k4 + 1]);
        float2 v2 = __half22float2(v[4 * k4 + 2]);
        float2 v3 = __half22float2(v[4 * k4 + 3]);
        ox = fmaf(a4.x, v0.x, ox);  oy = fmaf(a4.x, v0.y, oy);
        ox = fmaf(a4.y, v1.x, ox);  oy = fmaf(a4.y, v1.y, oy);
        ox = fmaf(a4.z, v2.x, ox);  oy = fmaf(a4.z, v2.y, oy);
        ox = fmaf(a4.w, v3.x, ox);  oy = fmaf(a4.w, v3.y, oy);
    }

    if (valid) {
        float invd = 1.0f / denom;
        *reinterpret_cast<float2*>(&out[node * OUT_DIM + 2 * hl]) =
            make_float2(ox * invd, oy * invd);
    }
}

extern "C" void kernel_launch(void* const* d_in, const int* in_sizes, int n_in,
                              void* d_out, int out_size)
{
    const float* h    = (const float*)d_in[0];   // [N, 128]
    const float* W    = (const float*)d_in[1];   // [32, 128]
    const float* beta = (const float*)d_in[2];   // [1]
    const int*   src  = (const int*)d_in[3];     // [E]
    float* out = (float*)d_out;

    int N = in_sizes[0] / IN_DIM;                // 100000
    int ntiles = (N + 63) / 64;                  // 1563

    cudaFuncSetAttribute(gemm_wmma_kernel,
                         cudaFuncAttributeMaxDynamicSharedMemorySize,
                         GEMM_SMEM_BYTES);
    gemm_wmma_kernel<<<ntiles, 256, GEMM_SMEM_BYTES>>>(h, W, N);

    int nwarps  = (N + 1) / 2;
    int nblocks = (nwarps + 7) / 8;              // 8 warps / block
    edge_agg_kernel<<<nblocks, 256>>>(beta, src, out, N);
}

// round 12
// speedup vs baseline: 1.4642x; 1.3354x over previous
#include <cuda_runtime.h>
#include <cuda_fp16.h>
#include <mma.h>
#include <math.h>
#include <stdint.h>

using namespace nvcuda;

#define N_NODES   100000
#define DEG       16
#define IN_DIM    128
#define OUT_DIM   32
#define EPS       1e-8f

// scratch (device globals: no allocation allowed in kernel_launch)
__device__ __half2 g_zh[N_NODES * (OUT_DIM / 2)];   // z rows in fp16 (only copy)
__device__ float   g_inorm[N_NODES];                // 1 / max(||z_i||, EPS)

// ---------------------------------------------------------------------------
// Kernel 1: z = h @ W^T via wmma FP16 (m16n16k16), fp32 accumulate, fused
// inverse row norms. fp16 mantissa (11 bits) == tf32 mantissa -> same error,
// half the smem / LDS wavefronts / k-steps.
// One CTA per 64-row tile (1563 CTAs), 256 threads = 8 warps.
// smem 26.1KB/CTA -> 6-8 CTAs/SM (48-64 warps/SM).
// Warp w: m-tile (w&3)*16, n-tile (w>>2)*16; 8 k-steps.
// Smem (halves, LDH2=136: 272B rows -> 4-float-equiv offset, conflict-free):
//   Ws  [32][136] @ 0      ( 8704 B)
//   hs  [64][136] @ 8704   (17408 B)   zsm [64][36] fp32 ALIASES hs
// total 26112 B.
// ---------------------------------------------------------------------------
#define LDH2 136
#define LDZ  36
#define GEMM_SMEM_BYTES 26112

__global__ __launch_bounds__(256) void gemm_wmma_kernel(
    const float* __restrict__ h, const float* __restrict__ W, int N)
{
    extern __shared__ char smraw[];
    __half* Ws  = reinterpret_cast<__half*>(smraw);           // [32][136]
    __half* hs  = reinterpret_cast<__half*>(smraw + 8704);    // [64][136]
    float*  zsm = reinterpret_cast<float*>(smraw + 8704);     // [64][36] alias

    const int tid  = threadIdx.x;
    const int wid  = tid >> 5;
    const int m0   = (wid & 3) * 16;
    const int n0   = (wid >> 2) * 16;
    const int row0 = blockIdx.x * 64;
    const unsigned FULL = 0xffffffffu;

    // ---- stage W -> fp16 smem (coalesced float4 -> 8B stores) ----
    const float4* W4 = reinterpret_cast<const float4*>(W);
    #pragma unroll
    for (int i = 0; i < 4; i++) {
        int f  = tid + i * 256;            // float4 index 0..1023
        int n  = f >> 5;
        int k4 = f & 31;
        float4 v = __ldg(&W4[n * 32 + k4]);
        __half2 hx[2] = { __floats2half2_rn(v.x, v.y),
                          __floats2half2_rn(v.z, v.w) };
        *reinterpret_cast<uint2*>(&Ws[n * LDH2 + k4 * 4]) =
            *reinterpret_cast<const uint2*>(hx);
    }

    // ---- load 64-row h tile -> fp16 smem ----
    const float4* h4 = reinterpret_cast<const float4*>(h);
    #pragma unroll
    for (int i = 0; i < 8; i++) {
        int f    = tid + i * 256;          // float4 index 0..2047
        int r    = f >> 5;                 // 0..63
        int k4   = f & 31;                 // 0..31
        int grow = row0 + r;
        if (grow >= N) grow = N - 1;
        float4 v = __ldg(&h4[grow * 32 + k4]);
        __half2 hx[2] = { __floats2half2_rn(v.x, v.y),
                          __floats2half2_rn(v.z, v.w) };
        *reinterpret_cast<uint2*>(&hs[r * LDH2 + k4 * 4]) =
            *reinterpret_cast<const uint2*>(hx);
    }
    __syncthreads();

    // ---- wmma: 1 m-tile x 1 n-tile x 8 k-steps per warp ----
    wmma::fragment<wmma::accumulator, 16, 16, 16, float> c0;
    wmma::fill_fragment(c0, 0.0f);
    wmma::fragment<wmma::matrix_a, 16, 16, 16, __half, wmma::row_major> a0;
    wmma::fragment<wmma::matrix_b, 16, 16, 16, __half, wmma::col_major> b0;
    #pragma unroll
    for (int ks = 0; ks < 8; ks++) {
        wmma::load_matrix_sync(a0, &hs[m0 * LDH2 + ks * 16], LDH2);
        wmma::load_matrix_sync(b0, &Ws[n0 * LDH2 + ks * 16], LDH2);
        wmma::mma_sync(c0, a0, b0, c0);
    }
    __syncthreads();                       // hs reads done -> zsm may overwrite

    wmma::store_matrix_sync(&zsm[m0 * LDZ + n0], c0, LDZ, wmma::mem_row_major);
    __syncthreads();

    // ---- epilogue: fp16 z (coalesced) + inverse norms (from fp32 acc) ----
    // thread t: row = t>>2 (0..63), quarter q = t&3 -> cols q*8..q*8+7
    int row = tid >> 2;
    int q   = tid & 3;
    float4 z4[2];
    z4[0] = *reinterpret_cast<const float4*>(&zsm[row * LDZ + q * 8]);
    z4[1] = *reinterpret_cast<const float4*>(&zsm[row * LDZ + q * 8 + 4]);
    float ss = z4[0].x * z4[0].x + z4[0].y * z4[0].y
             + z4[0].z * z4[0].z + z4[0].w * z4[0].w
             + z4[1].x * z4[1].x + z4[1].y * z4[1].y
             + z4[1].z * z4[1].z + z4[1].w * z4[1].w;
    ss += __shfl_xor_sync(FULL, ss, 1);
    ss += __shfl_xor_sync(FULL, ss, 2);
    int grow = row0 + row;
    if (grow < N) {
        __half2 hx[4];
        hx[0] = __floats2half2_rn(z4[0].x, z4[0].y);
        hx[1] = __floats2half2_rn(z4[0].z, z4[0].w);
        hx[2] = __floats2half2_rn(z4[1].x, z4[1].y);
        hx[3] = __floats2half2_rn(z4[1].z, z4[1].w);
        *reinterpret_cast<uint4*>(&g_zh[grow * 16 + q * 4]) =
            *reinterpret_cast<const uint4*>(hx);
        if (q == 0)
            g_inorm[grow] = 1.0f / fmaxf(sqrtf(ss), EPS);
    }
}

// ---------------------------------------------------------------------------
// Kernel 2: per-node cosine attention + softmax + weighted aggregation.
// Half-warp per node; v AND zd gathered as __half2. All math in fp32.
// (unchanged from R11 — at its L1-wavefront floor)
// ---------------------------------------------------------------------------
__global__ __launch_bounds__(256) void edge_agg_kernel(
    const float* __restrict__ beta_p, const int* __restrict__ src,
    float* __restrict__ out, int N)
{
    __shared__ float alpha_sm[8][32];

    const int warp_id = (blockIdx.x * blockDim.x + threadIdx.x) >> 5;
    if (warp_id * 2 >= N) return;

    const int w    = threadIdx.x >> 5;
    const int lane = threadIdx.x & 31;
    const int half = lane >> 4;
    const int hl   = lane & 15;
    int node = warp_id * 2 + half;
    const bool valid = (node < N);
    if (!valid) node = N - 1;

    const unsigned FULL = 0xffffffffu;
    const float beta = __ldg(beta_p);

    const float2 zd    = __half22float2(g_zh[node * 16 + hl]);
    const float inv_nd = g_inorm[node];

    const int4* sp = reinterpret_cast<const int4*>(src + node * DEG);
    int4 s0 = __ldg(sp + 0);
    int4 s1 = __ldg(sp + 1);
    int4 s2 = __ldg(sp + 2);
    int4 s3 = __ldg(sp + 3);
    int si[DEG] = { s0.x, s0.y, s0.z, s0.w,  s1.x, s1.y, s1.z, s1.w,
                    s2.x, s2.y, s2.z, s2.w,  s3.x, s3.y, s3.z, s3.w };

    // own-edge src (coalesced) -> per-edge cosine scale
    const int sid_own = __ldg(src + node * DEG + hl);
    const float cc = __ldg(&g_inorm[sid_own]) * inv_nd;

    // 4-bit bit-reversal (involution): lane hl ends holding edge hl's dot
    constexpr int REV4[16] = {0,8,4,12, 2,10,6,14, 1,9,5,13, 3,11,7,15};

    // gather src rows in fp16 (64B per row: 2 sectors)
    __half2 v[DEG];
    #pragma unroll
    for (int k = 0; k < DEG; k++)
        v[k] = g_zh[si[REV4[k]] * 16 + hl];

    float p[DEG];
    #pragma unroll
    for (int k = 0; k < DEG; k++) {
        float2 vf = __half22float2(v[k]);
        p[k] = fmaf(vf.x, zd.x, vf.y * zd.y);
    }

    const bool b8 = (hl & 8) != 0;
    const bool b4 = (hl & 4) != 0;
    const bool b2 = (hl & 2) != 0;
    const bool b1 = (hl & 1) != 0;

    float s[8];
    #pragma unroll
    for (int i = 0; i < 8; i++) {
        float a = p[2 * i]     + __shfl_xor_sync(FULL, p[2 * i], 8);
        float b = p[2 * i + 1] + __shfl_xor_sync(FULL, p[2 * i + 1], 8);
        s[i] = b8 ? b : a;
    }
    float q[4];
    #pragma unroll
    for (int i = 0; i < 4; i++) {
        float a = s[2 * i]     + __shfl_xor_sync(FULL, s[2 * i], 4);
        float b = s[2 * i + 1] + __shfl_xor_sync(FULL, s[2 * i + 1], 4);
        q[i] = b4 ? b : a;
    }
    float w2_[2];
    #pragma unroll
    for (int i = 0; i < 2; i++) {
        float a = q[2 * i]     + __shfl_xor_sync(FULL, q[2 * i], 2);
        float b = q[2 * i + 1] + __shfl_xor_sync(FULL, q[2 * i + 1], 2);
        w2_[i] = b2 ? b : a;
    }
    float xa = w2_[0] + __shfl_xor_sync(FULL, w2_[0], 1);
    float xb = w2_[1] + __shfl_xor_sync(FULL, w2_[1], 1);
    float dotv = b1 ? xb : xa;                 // raw dot of edge `hl`

    // softmax weight: exp(-beta(1-cos)) -> exp(beta*cos) (constant cancels);
    // beta in [0,1), cos <= 1 -> no overflow, no max subtraction needed.
    float esc = __expf(beta * (dotv * cc));

    // publish esc in REV4-permuted order: slot j holds esc of edge REV4[j]
    alpha_sm[w][(lane & 16) | REV4[hl]] = esc;
    __syncwarp(FULL);

    // aggregation + denom accumulated from the same smem reads (no shfl)
    const float4* ap = reinterpret_cast<const float4*>(&alpha_sm[w][lane & 16]);
    float ox = 0.f, oy = 0.f, denom = 0.f;
    #pragma unroll
    for (int k4 = 0; k4 < 4; k4++) {
        float4 a4 = ap[k4];
        denom += (a4.x + a4.y) + (a4.z + a4.w);
        float2 v0 = __half22float2(v[4 * k4 + 0]);
        float2 v1 = __half22float2(v[4 * k4 + 1]);
        float2 v2 = __half22float2(v[4 * k4 + 2]);
        float2 v3 = __half22float2(v[4 * k4 + 3]);
        ox = fmaf(a4.x, v0.x, ox);  oy = fmaf(a4.x, v0.y, oy);
        ox = fmaf(a4.y, v1.x, ox);  oy = fmaf(a4.y, v1.y, oy);
        ox = fmaf(a4.z, v2.x, ox);  oy = fmaf(a4.z, v2.y, oy);
        ox = fmaf(a4.w, v3.x, ox);  oy = fmaf(a4.w, v3.y, oy);
    }

    if (valid) {
        float invd = 1.0f / denom;
        *reinterpret_cast<float2*>(&out[node * OUT_DIM + 2 * hl]) =
            make_float2(ox * invd, oy * invd);
    }
}

extern "C" void kernel_launch(void* const* d_in, const int* in_sizes, int n_in,
                              void* d_out, int out_size)
{
    const float* h    = (const float*)d_in[0];   // [N, 128]
    const float* W    = (const float*)d_in[1];   // [32, 128]
    const float* beta = (const float*)d_in[2];   // [1]
    const int*   src  = (const int*)d_in[3];     // [E]
    float* out = (float*)d_out;

    int N = in_sizes[0] / IN_DIM;                // 100000
    int ntiles = (N + 63) / 64;                  // 1563

    cudaFuncSetAttribute(gemm_wmma_kernel,
                         cudaFuncAttributeMaxDynamicSharedMemorySize,
                         GEMM_SMEM_BYTES);
    gemm_wmma_kernel<<<ntiles, 256, GEMM_SMEM_BYTES>>>(h, W, N);

    int nwarps  = (N + 1) / 2;
    int nblocks = (nwarps + 7) / 8;              // 8 warps / block
    edge_agg_kernel<<<nblocks, 256>>>(beta, src, out, N);
}